// round 5
// baseline (speedup 1.0000x reference)
#include <cuda_runtime.h>
#include <cstdint>
#include <math.h>

#define NUM_ROIS 333
#define BATCH    512
#define N_REG    300
#define N_CLS    180
#define EPSV     1e-5f
#define SLOPEV   0.3f
#define SPLITK   24

// -------- static device scratch (no allocations allowed) --------
__device__ int   g_base[NUM_ROIS];
__device__ int   g_size[NUM_ROIS];
__device__ int   g_red [NUM_ROIS];
__device__ int   g_off [NUM_ROIS];
__device__ int   g_order[NUM_ROIS];
__device__ float g_partial[SPLITK * BATCH * N_REG];

typedef unsigned long long u64;

__device__ __forceinline__ u64 fma2(u64 a, u64 b, u64 c) {
    u64 d;
    asm("fma.rn.f32x2 %0, %1, %2, %3;" : "=l"(d) : "l"(a), "l"(b), "l"(c));
    return d;
}
__device__ __forceinline__ float2 unpack2(u64 v) {
    float lo, hi;
    asm("mov.b64 {%0, %1}, %2;" : "=f"(lo), "=f"(hi) : "l"(v));
    return make_float2(lo, hi);
}
__device__ __forceinline__ unsigned sptr(const void* p) {
    return (unsigned)__cvta_generic_to_shared(p);
}
__device__ __forceinline__ void cpa4(unsigned dst, const void* src) {
    asm volatile("cp.async.ca.shared.global [%0], [%1], 4;" :: "r"(dst), "l"(src));
}
__device__ __forceinline__ void cp_commit() { asm volatile("cp.async.commit_group;"); }
__device__ __forceinline__ void cp_wait1()  { asm volatile("cp.async.wait_group 1;" ::: "memory"); }

// ============================================================
// Setup: per-ROI meta + size-descending schedule
// ============================================================
__global__ void setup_kernel(const int* __restrict__ idx,
                             const int* __restrict__ src_index,
                             int max_in, int max_out, int total, int C) {
    int t = threadIdx.x;
    __shared__ int s_size[NUM_ROIS];
    for (int r = t; r < NUM_ROIS; r += blockDim.x) {
        const int* row = idx + (size_t)r * max_in;
        int lo = 0, hi = max_in;
        while (lo < hi) {                    // first k with row[k] == total
            int mid = (lo + hi) >> 1;
            if (row[mid] == total) hi = mid; else lo = mid + 1;
        }
        g_size[r] = lo;
        s_size[r] = lo;
        g_base[r] = row[0];
    }
    __shared__ int cnt[NUM_ROIS];
    for (int r = t; r < NUM_ROIS; r += blockDim.x) cnt[r] = 0;
    __syncthreads();
    for (int p = t; p < C; p += blockDim.x)
        atomicAdd(&cnt[src_index[p] / max_out], 1);
    __syncthreads();
    if (t == 0) {
        int off = 0;
        for (int r = 0; r < NUM_ROIS; r++) {
            g_red[r] = cnt[r];
            g_off[r] = off;
            off += cnt[r];
        }
    }
    // size-descending rank (deterministic tie-break by index)
    for (int r = t; r < NUM_ROIS; r += blockDim.x) {
        int sz = s_size[r];
        int rank = 0;
        for (int j = 0; j < NUM_ROIS; j++) {
            int sj = s_size[j];
            if (sj > sz || (sj == sz && j < r)) rank++;
        }
        g_order[rank] = r;
    }
}

// ============================================================
// Stage A: per-ROI GEMM (256 batch x 32 out) + BN + leaky -> concat_out
// batch-packed f32x2, W duplicated in smem, cp.async double-buffered
// grid: (NUM_ROIS sorted, 2 batch halves, 2 out tiles)
// ============================================================
#define A_XSTR 260                       // 256 data + 4 pad
#define A_WSTR 100                       // 8 grp * 12 + 4 pad
#define A_XSZ  (16 * A_XSTR)             // 4160
#define A_WSZ  (16 * A_WSTR)             // 1600
#define A_SMEM ((2 * A_XSZ + 2 * A_WSZ) * 4)   // 46080 bytes

__global__ __launch_bounds__(256, 2)
void roi_enc_kernel(const float* __restrict__ x, const float* __restrict__ W_enc,
                    const float* __restrict__ b_enc, const float* __restrict__ gamma,
                    const float* __restrict__ beta, const float* __restrict__ rmean,
                    const float* __restrict__ rvar, float* __restrict__ concat_out,
                    int total, int max_in, int max_out, int C)
{
    extern __shared__ float sm[];
    float* Xs = sm;                       // [2][A_XSZ]  Xs[st][k][b]
    float* Ws = sm + 2 * A_XSZ;           // [2][A_WSZ]  dup pairs per o

    const int r    = g_order[blockIdx.x];
    const int b0   = blockIdx.y * 256;
    const int ot   = blockIdx.z * 32;
    const int size = g_size[r];
    const int red  = g_red[r];
    const int base = g_base[r];
    const int ooff = g_off[r];
    if (ot >= red) return;                // uniform per block

    const int tid = threadIdx.x;
    const int tb  = tid >> 3;             // 0..31 batch group (8 b each)
    const int to  = tid & 7;              // 0..7  out group   (4 o each)
    const int fk  = tid & 15;             // fill: fixed k within tile
    const int fr0 = tid >> 4;             // fill: base row

    const float* xg = x + (size_t)b0 * total + base;
    const float* wg = W_enc + (size_t)r * max_out * max_in;
    const unsigned xs_u = sptr(Xs);

    const int nt = (size + 15) >> 4;

    u64 acc[4][4];
    #pragma unroll
    for (int i = 0; i < 4; i++)
        #pragma unroll
        for (int j = 0; j < 4; j++) acc[i][j] = 0ull;

    float wr[2];

    auto fillX = [&](int t, int st) {
        int kg = t * 16 + fk;
        if (kg < size) {
            const float* src = xg + kg;
            unsigned dst = xs_u + (unsigned)(st * A_XSZ + fk * A_XSTR) * 4u;
            #pragma unroll
            for (int it = 0; it < 16; it++) {
                int b = fr0 + it * 16;
                cpa4(dst + (unsigned)b * 4u, src + (size_t)b * total);
            }
        } else {
            float* d = Xs + st * A_XSZ + fk * A_XSTR;
            #pragma unroll
            for (int it = 0; it < 16; it++) d[fr0 + it * 16] = 0.f;
        }
    };
    auto ldgW = [&](int t) {
        int kg = t * 16 + fk;
        #pragma unroll
        for (int it = 0; it < 2; it++) {
            int o = ot + fr0 + it * 16;
            wr[it] = (o < max_out && kg < size) ? wg[(size_t)o * max_in + kg] : 0.f;
        }
    };
    auto stsW = [&](int st) {
        float* d = Ws + st * A_WSZ + fk * A_WSTR;
        #pragma unroll
        for (int it = 0; it < 2; it++) {
            int o = fr0 + it * 16;     // local o in [0,32)
            *(float2*)(d + (o >> 2) * 12 + (o & 3) * 2) = make_float2(wr[it], wr[it]);
        }
    };
    auto compute = [&](int st) {
        const float* xb = Xs + st * A_XSZ + tb * 8;
        const float* wb = Ws + st * A_WSZ + to * 12;
        #pragma unroll
        for (int kk = 0; kk < 16; kk++) {
            const ulonglong2* xp = (const ulonglong2*)(xb + kk * A_XSTR);
            const ulonglong2* wp = (const ulonglong2*)(wb + kk * A_WSTR);
            ulonglong2 x01 = xp[0], x23 = xp[1];
            ulonglong2 w01 = wp[0], w23 = wp[1];
            u64 xv[4] = {x01.x, x01.y, x23.x, x23.y};
            u64 wv[4] = {w01.x, w01.y, w23.x, w23.y};
            #pragma unroll
            for (int i = 0; i < 4; i++)
                #pragma unroll
                for (int j = 0; j < 4; j++)
                    acc[i][j] = fma2(xv[i], wv[j], acc[i][j]);
        }
    };

    // ---- pipelined mainloop (2-stage) ----
    fillX(0, 0); cp_commit();
    ldgW(0);
    if (nt > 1) fillX(1, 1);
    cp_commit();
    stsW(0);
    if (nt > 1) ldgW(1);
    cp_wait1();
    __syncthreads();

    for (int t = 0; t < nt; t++) {
        int st = t & 1;
        compute(st);
        __syncthreads();
        if (t + 2 < nt) fillX(t + 2, st);
        cp_commit();
        if (t + 1 < nt) stsW(st ^ 1);
        if (t + 2 < nt) ldgW(t + 2);
        cp_wait1();
        __syncthreads();
    }

    // ---- epilogue: BN + leaky, smem transpose, coalesced store ----
    float* Ysm = sm;   // reuse: 128*33 = 4224 floats
    for (int half = 0; half < 2; half++) {
        __syncthreads();
        if ((tb >> 4) == half) {
            int bl = (tb & 15) * 8;
            #pragma unroll
            for (int j = 0; j < 4; j++) {
                int og = ot + to * 4 + j;
                if (og < red) {
                    size_t po = (size_t)r * max_out + og;
                    float be  = b_enc[po];
                    float ga  = gamma[po];
                    float bt  = beta[po];
                    float mn  = rmean[po];
                    float inv = rsqrtf(rvar[po] + EPSV);
                    int ol = to * 4 + j;
                    #pragma unroll
                    for (int i = 0; i < 4; i++) {
                        float2 v = unpack2(acc[i][j]);
                        float y0 = ga * (v.x + be - mn) * inv + bt;
                        float y1 = ga * (v.y + be - mn) * inv + bt;
                        y0 = (y0 > 0.f) ? y0 : SLOPEV * y0;
                        y1 = (y1 > 0.f) ? y1 : SLOPEV * y1;
                        Ysm[(bl + 2 * i)     * 33 + ol] = y0;
                        Ysm[(bl + 2 * i + 1) * 33 + ol] = y1;
                    }
                }
            }
        }
        __syncthreads();
        for (int p = tid; p < 128 * 32; p += 256) {
            int bl = p >> 5, o = p & 31;
            int og = ot + o;
            if (og < red)
                concat_out[(size_t)(b0 + half * 128 + bl) * C + ooff + og] =
                    Ysm[bl * 33 + o];
        }
    }
}

// ============================================================
// Stage B: reg_out partials = concat_out @ W_reg^T  (split-K)
// 128x128 tile, FFMA2 structure
// ============================================================
#define B_ASTR 132                       // 128 + 4 pad
#define B_WSTR 324                       // 16 grp * 20 + 4 pad
#define B_ASZ  (16 * B_ASTR)             // 2112
#define B_WSZ  (16 * B_WSTR)             // 5184
#define B_SMEM ((2 * B_ASZ + 2 * B_WSZ) * 4)   // 58368 bytes

__global__ __launch_bounds__(256, 2)
void reg_gemm_kernel(const float* __restrict__ A, const float* __restrict__ Wr, int C)
{
    extern __shared__ float sm[];
    float* As = sm;
    float* Bs = sm + 2 * B_ASZ;

    const int m0 = blockIdx.x * 128;
    const int n0 = blockIdx.y * 128;
    const int s  = blockIdx.z;
    const int chunk = (C + SPLITK - 1) / SPLITK;
    const int kbeg  = s * chunk;
    const int kend  = min(C, kbeg + chunk);
    const int klen  = kend - kbeg;

    const int tid = threadIdx.x;
    const int tb  = tid >> 4;             // 0..15 m group
    const int to  = tid & 15;             // 0..15 n group
    const int fk  = tid & 15;
    const int fr0 = tid >> 4;

    const unsigned as_u = sptr(As);

    u64 acc[4][8];
    #pragma unroll
    for (int i = 0; i < 4; i++)
        #pragma unroll
        for (int j = 0; j < 8; j++) acc[i][j] = 0ull;

    if (klen > 0) {
        const int nt = (klen + 15) >> 4;
        float wr[8];

        auto fillA = [&](int t, int st) {
            int kg = kbeg + t * 16 + fk;
            if (kg < kend) {
                unsigned dst = as_u + (unsigned)(st * B_ASZ + fk * B_ASTR) * 4u;
                const float* src = A + kg;
                #pragma unroll
                for (int it = 0; it < 8; it++) {
                    int m = fr0 + it * 16;
                    cpa4(dst + (unsigned)m * 4u, src + (size_t)(m0 + m) * C);
                }
            } else {
                float* d = As + st * B_ASZ + fk * B_ASTR;
                #pragma unroll
                for (int it = 0; it < 8; it++) d[fr0 + it * 16] = 0.f;
            }
        };
        auto ldgW = [&](int t) {
            int kg = kbeg + t * 16 + fk;
            #pragma unroll
            for (int it = 0; it < 8; it++) {
                int n = n0 + fr0 + it * 16;
                wr[it] = (n < N_REG && kg < kend) ? Wr[(size_t)n * C + kg] : 0.f;
            }
        };
        auto stsW = [&](int st) {
            float* d = Bs + st * B_WSZ + fk * B_WSTR;
            #pragma unroll
            for (int it = 0; it < 8; it++) {
                int l = fr0 + it * 16;
                *(float2*)(d + (l >> 3) * 20 + (l & 7) * 2) = make_float2(wr[it], wr[it]);
            }
        };
        auto compute = [&](int st) {
            const float* xb = As + st * B_ASZ + tb * 8;
            const float* wb = Bs + st * B_WSZ + to * 20;
            #pragma unroll
            for (int kk = 0; kk < 16; kk++) {
                const ulonglong2* xp = (const ulonglong2*)(xb + kk * B_ASTR);
                const ulonglong2* wp = (const ulonglong2*)(wb + kk * B_WSTR);
                ulonglong2 x01 = xp[0], x23 = xp[1];
                ulonglong2 w01 = wp[0], w23 = wp[1], w45 = wp[2], w67 = wp[3];
                u64 xv[4] = {x01.x, x01.y, x23.x, x23.y};
                u64 wv[8] = {w01.x, w01.y, w23.x, w23.y, w45.x, w45.y, w67.x, w67.y};
                #pragma unroll
                for (int i = 0; i < 4; i++)
                    #pragma unroll
                    for (int j = 0; j < 8; j++)
                        acc[i][j] = fma2(xv[i], wv[j], acc[i][j]);
            }
        };

        fillA(0, 0); cp_commit();
        ldgW(0);
        if (nt > 1) fillA(1, 1);
        cp_commit();
        stsW(0);
        if (nt > 1) ldgW(1);
        cp_wait1();
        __syncthreads();

        for (int t = 0; t < nt; t++) {
            int st = t & 1;
            compute(st);
            __syncthreads();
            if (t + 2 < nt) fillA(t + 2, st);
            cp_commit();
            if (t + 1 < nt) stsW(st ^ 1);
            if (t + 2 < nt) ldgW(t + 2);
            cp_wait1();
            __syncthreads();
        }
    }

    #pragma unroll
    for (int j = 0; j < 8; j++) {
        int n = n0 + to * 8 + j;
        if (n < N_REG) {
            #pragma unroll
            for (int i = 0; i < 4; i++) {
                float2 v = unpack2(acc[i][j]);
                int m = m0 + tb * 8 + 2 * i;
                g_partial[((size_t)s * BATCH + m)     * N_REG + n] = v.x;
                g_partial[((size_t)s * BATCH + m + 1) * N_REG + n] = v.y;
            }
        }
    }
}

// ============================================================
// Stage C: split-K reduce + bias -> reg_out ; cls GEMV ; softmax
// 32 blocks x 16 rows
// ============================================================
#define C_ROWS 16

__global__ __launch_bounds__(256)
void cls_softmax_kernel(const float* __restrict__ b_reg,
                        const float* __restrict__ W_cls,
                        const float* __restrict__ b_cls,
                        float* __restrict__ reg_out,
                        float* __restrict__ y_pred) {
    __shared__ float rows[C_ROWS][304];
    __shared__ float lg[C_ROWS][192];

    const int m0  = blockIdx.x * C_ROWS;
    const int tid = threadIdx.x;

    // phase 1: split-K reduce + bias -> rows (smem) + reg_out (gmem)
    for (int p = tid; p < C_ROWS * N_REG; p += 256) {
        int mi = p / N_REG, n = p % N_REG;
        int m  = m0 + mi;
        float sv = b_reg[n];
        #pragma unroll
        for (int k = 0; k < SPLITK; k++)
            sv += g_partial[((size_t)k * BATCH + m) * N_REG + n];
        rows[mi][n] = sv;
        reg_out[(size_t)m * N_REG + n] = sv;
    }
    __syncthreads();

    // phase 2: logits = rows @ W_cls^T + b_cls  (float4 streaming)
    for (int q = tid; q < C_ROWS * N_CLS; q += 256) {
        int mi = q / N_CLS, n = q % N_CLS;
        const float4* w  = (const float4*)(W_cls + (size_t)n * N_REG);
        const float4* rr = (const float4*)rows[mi];
        float s = b_cls[n];
        #pragma unroll 5
        for (int k4 = 0; k4 < N_REG / 4; k4++) {
            float4 a = rr[k4];
            float4 b = __ldg(&w[k4]);
            s = fmaf(a.x, b.x, s);
            s = fmaf(a.y, b.y, s);
            s = fmaf(a.z, b.z, s);
            s = fmaf(a.w, b.w, s);
        }
        lg[mi][n] = s;
    }
    __syncthreads();

    // phase 3: softmax, one warp per 2 rows
    int w = tid >> 5, lane = tid & 31;
    for (int mi = 2 * w; mi < 2 * w + 2; mi++) {
        float mx = -1e30f;
        for (int n = lane; n < N_CLS; n += 32) mx = fmaxf(mx, lg[mi][n]);
        #pragma unroll
        for (int off = 16; off > 0; off >>= 1)
            mx = fmaxf(mx, __shfl_xor_sync(0xffffffff, mx, off));
        float sum = 0.f;
        for (int n = lane; n < N_CLS; n += 32) {
            float e = expf(lg[mi][n] - mx);
            lg[mi][n] = e;
            sum += e;
        }
        #pragma unroll
        for (int off = 16; off > 0; off >>= 1)
            sum += __shfl_xor_sync(0xffffffff, sum, off);
        float inv = 1.f / sum;
        for (int n = lane; n < N_CLS; n += 32)
            y_pred[(size_t)(m0 + mi) * N_CLS + n] = lg[mi][n] * inv;
    }
}

// ============================================================
// Launch
// ============================================================
extern "C" void kernel_launch(void* const* d_in, const int* in_sizes, int n_in,
                              void* d_out, int out_size) {
    const float* x     = (const float*)d_in[0];
    const float* W_enc = (const float*)d_in[1];
    const float* b_enc = (const float*)d_in[2];
    const float* gamma = (const float*)d_in[3];
    const float* beta  = (const float*)d_in[4];
    const float* rmean = (const float*)d_in[5];
    const float* rvar  = (const float*)d_in[6];
    const float* W_reg = (const float*)d_in[7];
    const float* b_reg = (const float*)d_in[8];
    const float* W_cls = (const float*)d_in[9];
    const float* b_cls = (const float*)d_in[10];
    const int*   idx   = (const int*)d_in[11];
    const int*   srci  = (const int*)d_in[12];

    const int total   = in_sizes[0] / BATCH;
    const int max_out = in_sizes[2] / NUM_ROIS;
    const int max_in  = in_sizes[11] / NUM_ROIS;
    const int C       = in_sizes[12];

    float* out        = (float*)d_out;
    float* concat_out = out;
    float* reg_out    = out + (size_t)BATCH * C;
    float* y_pred     = reg_out + (size_t)BATCH * N_REG;

    cudaFuncSetAttribute(roi_enc_kernel,
                         cudaFuncAttributeMaxDynamicSharedMemorySize, A_SMEM);
    cudaFuncSetAttribute(reg_gemm_kernel,
                         cudaFuncAttributeMaxDynamicSharedMemorySize, B_SMEM);

    setup_kernel<<<1, 512>>>(idx, srci, max_in, max_out, total, C);

    dim3 gA(NUM_ROIS, BATCH / 256, 2);
    roi_enc_kernel<<<gA, 256, A_SMEM>>>(x, W_enc, b_enc, gamma, beta, rmean, rvar,
                                        concat_out, total, max_in, max_out, C);

    dim3 gB(BATCH / 128, (N_REG + 127) / 128, SPLITK);
    reg_gemm_kernel<<<gB, 256, B_SMEM>>>(concat_out, W_reg, C);

    cls_softmax_kernel<<<BATCH / C_ROWS, 256>>>(b_reg, W_cls, b_cls, reg_out, y_pred);
}

// round 7
// speedup vs baseline: 1.2446x; 1.2446x over previous
#include <cuda_runtime.h>
#include <cstdint>
#include <math.h>

#define NUM_ROIS 333
#define BATCH    512
#define N_REG    300
#define N_CLS    180
#define EPSV     1e-5f
#define SLOPEV   0.3f
#define SPLITK   24

// -------- static device scratch (no allocations allowed) --------
__device__ int   g_base[NUM_ROIS];
__device__ int   g_size[NUM_ROIS];
__device__ int   g_red [NUM_ROIS];
__device__ int   g_off [NUM_ROIS];
__device__ int   g_order[NUM_ROIS];
__device__ float g_partial[SPLITK * BATCH * N_REG];

typedef unsigned long long u64;

__device__ __forceinline__ u64 fma2(u64 a, u64 b, u64 c) {
    u64 d;
    asm("fma.rn.f32x2 %0, %1, %2, %3;" : "=l"(d) : "l"(a), "l"(b), "l"(c));
    return d;
}
__device__ __forceinline__ float2 unpack2(u64 v) {
    float lo, hi;
    asm("mov.b64 {%0, %1}, %2;" : "=f"(lo), "=f"(hi) : "l"(v));
    return make_float2(lo, hi);
}
__device__ __forceinline__ unsigned sptr(const void* p) {
    return (unsigned)__cvta_generic_to_shared(p);
}
__device__ __forceinline__ void cpa4(unsigned dst, const void* src) {
    asm volatile("cp.async.ca.shared.global [%0], [%1], 4;" :: "r"(dst), "l"(src));
}
__device__ __forceinline__ void cp_commit() { asm volatile("cp.async.commit_group;"); }
__device__ __forceinline__ void cp_wait1()  { asm volatile("cp.async.wait_group 1;" ::: "memory"); }

// ============================================================
// Setup: per-ROI meta + size-descending schedule
// ============================================================
__global__ void setup_kernel(const int* __restrict__ idx,
                             const int* __restrict__ src_index,
                             int max_in, int max_out, int total, int C) {
    int t = threadIdx.x;
    __shared__ int s_size[NUM_ROIS];
    for (int r = t; r < NUM_ROIS; r += blockDim.x) {
        const int* row = idx + (size_t)r * max_in;
        int lo = 0, hi = max_in;
        while (lo < hi) {                    // first k with row[k] == total
            int mid = (lo + hi) >> 1;
            if (row[mid] == total) hi = mid; else lo = mid + 1;
        }
        g_size[r] = lo;
        s_size[r] = lo;
        g_base[r] = row[0];
    }
    __shared__ int cnt[NUM_ROIS];
    for (int r = t; r < NUM_ROIS; r += blockDim.x) cnt[r] = 0;
    __syncthreads();
    for (int p = t; p < C; p += blockDim.x)
        atomicAdd(&cnt[src_index[p] / max_out], 1);
    __syncthreads();
    if (t == 0) {
        int off = 0;
        for (int r = 0; r < NUM_ROIS; r++) {
            g_red[r] = cnt[r];
            g_off[r] = off;
            off += cnt[r];
        }
    }
    // size-descending rank (deterministic tie-break by index)
    for (int r = t; r < NUM_ROIS; r += blockDim.x) {
        int sz = s_size[r];
        int rank = 0;
        for (int j = 0; j < NUM_ROIS; j++) {
            int sj = s_size[j];
            if (sj > sz || (sj == sz && j < r)) rank++;
        }
        g_order[rank] = r;
    }
}

// ============================================================
// Stage A: per-ROI GEMM (256 batch x 32 out) + BN + leaky -> concat_out
// batch-packed f32x2, W duplicated in smem, cp.async double-buffered
// grid: (NUM_ROIS sorted, 2 batch halves, 2 out tiles)
// ============================================================
#define A_XSTR 260                       // 256 data + 4 pad
#define A_WSTR 100                       // 8 grp * 12 + 4 pad
#define A_XSZ  (16 * A_XSTR)             // 4160
#define A_WSZ  (16 * A_WSTR)             // 1600
#define A_SMEM ((2 * A_XSZ + 2 * A_WSZ) * 4)   // 46080 bytes

__global__ __launch_bounds__(256, 2)
void roi_enc_kernel(const float* __restrict__ x, const float* __restrict__ W_enc,
                    const float* __restrict__ b_enc, const float* __restrict__ gamma,
                    const float* __restrict__ beta, const float* __restrict__ rmean,
                    const float* __restrict__ rvar, float* __restrict__ concat_out,
                    int total, int max_in, int max_out, int C)
{
    extern __shared__ float sm[];
    float* Xs = sm;                       // [2][A_XSZ]  Xs[st][k][b]
    float* Ws = sm + 2 * A_XSZ;           // [2][A_WSZ]  dup pairs per o

    const int r    = g_order[blockIdx.x];
    const int b0   = blockIdx.y * 256;
    const int ot   = blockIdx.z * 32;
    const int size = g_size[r];
    const int red  = g_red[r];
    const int base = g_base[r];
    const int ooff = g_off[r];
    if (ot >= red) return;                // uniform per block

    const int tid = threadIdx.x;
    const int tb  = tid >> 3;             // 0..31 batch group (8 b each)
    const int to  = tid & 7;              // 0..7  out group   (4 o each)
    const int fk  = tid & 15;             // fill: fixed k within tile
    const int fr0 = tid >> 4;             // fill: base row

    const float* xg = x + (size_t)b0 * total + base;
    const float* wg = W_enc + (size_t)r * max_out * max_in;
    const unsigned xs_u = sptr(Xs);

    const int nt = (size + 15) >> 4;

    u64 acc[4][4];
    #pragma unroll
    for (int i = 0; i < 4; i++)
        #pragma unroll
        for (int j = 0; j < 4; j++) acc[i][j] = 0ull;

    float wr[2];

    auto fillX = [&](int t, int st) {
        int kg = t * 16 + fk;
        if (kg < size) {
            const float* src = xg + kg;
            unsigned dst = xs_u + (unsigned)(st * A_XSZ + fk * A_XSTR) * 4u;
            #pragma unroll
            for (int it = 0; it < 16; it++) {
                int b = fr0 + it * 16;
                cpa4(dst + (unsigned)b * 4u, src + (size_t)b * total);
            }
        } else {
            float* d = Xs + st * A_XSZ + fk * A_XSTR;
            #pragma unroll
            for (int it = 0; it < 16; it++) d[fr0 + it * 16] = 0.f;
        }
    };
    auto ldgW = [&](int t) {
        int kg = t * 16 + fk;
        #pragma unroll
        for (int it = 0; it < 2; it++) {
            int o = ot + fr0 + it * 16;
            wr[it] = (o < max_out && kg < size) ? wg[(size_t)o * max_in + kg] : 0.f;
        }
    };
    auto stsW = [&](int st) {
        float* d = Ws + st * A_WSZ + fk * A_WSTR;
        #pragma unroll
        for (int it = 0; it < 2; it++) {
            int o = fr0 + it * 16;     // local o in [0,32)
            *(float2*)(d + (o >> 2) * 12 + (o & 3) * 2) = make_float2(wr[it], wr[it]);
        }
    };
    auto compute = [&](int st) {
        const float* xb = Xs + st * A_XSZ + tb * 8;
        const float* wb = Ws + st * A_WSZ + to * 12;
        #pragma unroll
        for (int kk = 0; kk < 16; kk++) {
            const ulonglong2* xp = (const ulonglong2*)(xb + kk * A_XSTR);
            const ulonglong2* wp = (const ulonglong2*)(wb + kk * A_WSTR);
            ulonglong2 x01 = xp[0], x23 = xp[1];
            ulonglong2 w01 = wp[0], w23 = wp[1];
            u64 xv[4] = {x01.x, x01.y, x23.x, x23.y};
            u64 wv[4] = {w01.x, w01.y, w23.x, w23.y};
            #pragma unroll
            for (int i = 0; i < 4; i++)
                #pragma unroll
                for (int j = 0; j < 4; j++)
                    acc[i][j] = fma2(xv[i], wv[j], acc[i][j]);
        }
    };

    // ---- pipelined mainloop (2-stage) ----
    fillX(0, 0); cp_commit();
    ldgW(0);
    if (nt > 1) fillX(1, 1);
    cp_commit();
    stsW(0);
    if (nt > 1) ldgW(1);
    cp_wait1();
    __syncthreads();

    for (int t = 0; t < nt; t++) {
        int st = t & 1;
        compute(st);
        __syncthreads();
        if (t + 2 < nt) fillX(t + 2, st);
        cp_commit();
        if (t + 1 < nt) stsW(st ^ 1);
        if (t + 2 < nt) ldgW(t + 2);
        cp_wait1();
        __syncthreads();
    }

    // ---- epilogue: BN + leaky, smem transpose, coalesced store ----
    float* Ysm = sm;   // reuse: 128*33 = 4224 floats
    for (int half = 0; half < 2; half++) {
        __syncthreads();
        if ((tb >> 4) == half) {
            int bl = (tb & 15) * 8;
            #pragma unroll
            for (int j = 0; j < 4; j++) {
                int og = ot + to * 4 + j;
                if (og < red) {
                    size_t po = (size_t)r * max_out + og;
                    float be  = b_enc[po];
                    float ga  = gamma[po];
                    float bt  = beta[po];
                    float mn  = rmean[po];
                    float inv = rsqrtf(rvar[po] + EPSV);
                    int ol = to * 4 + j;
                    #pragma unroll
                    for (int i = 0; i < 4; i++) {
                        float2 v = unpack2(acc[i][j]);
                        float y0 = ga * (v.x + be - mn) * inv + bt;
                        float y1 = ga * (v.y + be - mn) * inv + bt;
                        y0 = (y0 > 0.f) ? y0 : SLOPEV * y0;
                        y1 = (y1 > 0.f) ? y1 : SLOPEV * y1;
                        Ysm[(bl + 2 * i)     * 33 + ol] = y0;
                        Ysm[(bl + 2 * i + 1) * 33 + ol] = y1;
                    }
                }
            }
        }
        __syncthreads();
        for (int p = tid; p < 128 * 32; p += 256) {
            int bl = p >> 5, o = p & 31;
            int og = ot + o;
            if (og < red)
                concat_out[(size_t)(b0 + half * 128 + bl) * C + ooff + og] =
                    Ysm[bl * 33 + o];
        }
    }
}

// ============================================================
// Stage B: reg_out partials = concat_out @ W_reg^T  (split-K)
// 128x128 tile, FFMA2 structure
// ============================================================
#define B_ASTR 132                       // 128 + 4 pad
#define B_WSTR 324                       // 16 grp * 20 + 4 pad
#define B_ASZ  (16 * B_ASTR)             // 2112
#define B_WSZ  (16 * B_WSTR)             // 5184
#define B_SMEM ((2 * B_ASZ + 2 * B_WSZ) * 4)   // 58368 bytes

__global__ __launch_bounds__(256, 2)
void reg_gemm_kernel(const float* __restrict__ A, const float* __restrict__ Wr, int C)
{
    extern __shared__ float sm[];
    float* As = sm;
    float* Bs = sm + 2 * B_ASZ;

    const int m0 = blockIdx.x * 128;
    const int n0 = blockIdx.y * 128;
    const int s  = blockIdx.z;
    const int chunk = (C + SPLITK - 1) / SPLITK;
    const int kbeg  = s * chunk;
    const int kend  = min(C, kbeg + chunk);
    const int klen  = kend - kbeg;

    const int tid = threadIdx.x;
    const int tb  = tid >> 4;             // 0..15 m group
    const int to  = tid & 15;             // 0..15 n group
    const int fk  = tid & 15;
    const int fr0 = tid >> 4;

    const unsigned as_u = sptr(As);

    u64 acc[4][8];
    #pragma unroll
    for (int i = 0; i < 4; i++)
        #pragma unroll
        for (int j = 0; j < 8; j++) acc[i][j] = 0ull;

    if (klen > 0) {
        const int nt = (klen + 15) >> 4;
        float wr[8];

        auto fillA = [&](int t, int st) {
            int kg = kbeg + t * 16 + fk;
            if (kg < kend) {
                unsigned dst = as_u + (unsigned)(st * B_ASZ + fk * B_ASTR) * 4u;
                const float* src = A + kg;
                #pragma unroll
                for (int it = 0; it < 8; it++) {
                    int m = fr0 + it * 16;
                    cpa4(dst + (unsigned)m * 4u, src + (size_t)(m0 + m) * C);
                }
            } else {
                float* d = As + st * B_ASZ + fk * B_ASTR;
                #pragma unroll
                for (int it = 0; it < 8; it++) d[fr0 + it * 16] = 0.f;
            }
        };
        auto ldgW = [&](int t) {
            int kg = kbeg + t * 16 + fk;
            #pragma unroll
            for (int it = 0; it < 8; it++) {
                int n = n0 + fr0 + it * 16;
                wr[it] = (n < N_REG && kg < kend) ? Wr[(size_t)n * C + kg] : 0.f;
            }
        };
        auto stsW = [&](int st) {
            float* d = Bs + st * B_WSZ + fk * B_WSTR;
            #pragma unroll
            for (int it = 0; it < 8; it++) {
                int l = fr0 + it * 16;
                *(float2*)(d + (l >> 3) * 20 + (l & 7) * 2) = make_float2(wr[it], wr[it]);
            }
        };
        auto compute = [&](int st) {
            const float* xb = As + st * B_ASZ + tb * 8;
            const float* wb = Bs + st * B_WSZ + to * 20;
            #pragma unroll
            for (int kk = 0; kk < 16; kk++) {
                const ulonglong2* xp = (const ulonglong2*)(xb + kk * B_ASTR);
                const ulonglong2* wp = (const ulonglong2*)(wb + kk * B_WSTR);
                ulonglong2 x01 = xp[0], x23 = xp[1];
                ulonglong2 w01 = wp[0], w23 = wp[1], w45 = wp[2], w67 = wp[3];
                u64 xv[4] = {x01.x, x01.y, x23.x, x23.y};
                u64 wv[8] = {w01.x, w01.y, w23.x, w23.y, w45.x, w45.y, w67.x, w67.y};
                #pragma unroll
                for (int i = 0; i < 4; i++)
                    #pragma unroll
                    for (int j = 0; j < 8; j++)
                        acc[i][j] = fma2(xv[i], wv[j], acc[i][j]);
            }
        };

        fillA(0, 0); cp_commit();
        ldgW(0);
        if (nt > 1) fillA(1, 1);
        cp_commit();
        stsW(0);
        if (nt > 1) ldgW(1);
        cp_wait1();
        __syncthreads();

        for (int t = 0; t < nt; t++) {
            int st = t & 1;
            compute(st);
            __syncthreads();
            if (t + 2 < nt) fillA(t + 2, st);
            cp_commit();
            if (t + 1 < nt) stsW(st ^ 1);
            if (t + 2 < nt) ldgW(t + 2);
            cp_wait1();
            __syncthreads();
        }
    }

    #pragma unroll
    for (int j = 0; j < 8; j++) {
        int n = n0 + to * 8 + j;
        if (n < N_REG) {
            #pragma unroll
            for (int i = 0; i < 4; i++) {
                float2 v = unpack2(acc[i][j]);
                int m = m0 + tb * 8 + 2 * i;
                g_partial[((size_t)s * BATCH + m)     * N_REG + n] = v.x;
                g_partial[((size_t)s * BATCH + m + 1) * N_REG + n] = v.y;
            }
        }
    }
}

// ============================================================
// Split-K reduce + bias -> reg_out  (600 CTAs, high MLP — proven 6us)
// ============================================================
__global__ void reg_reduce_kernel(const float* __restrict__ b_reg,
                                  float* __restrict__ reg_out) {
    int i = blockIdx.x * blockDim.x + threadIdx.x;
    if (i >= BATCH * N_REG) return;
    int n = i % N_REG;
    float sum = b_reg[n];
    #pragma unroll
    for (int k = 0; k < SPLITK; k++)
        sum += g_partial[(size_t)k * BATCH * N_REG + i];
    reg_out[i] = sum;
}

// ============================================================
// Stage C: cls GEMV + softmax.  128 CTAs x 4 rows.
// ============================================================
#define C_ROWS 4

__global__ __launch_bounds__(256)
void cls_softmax_kernel(const float* __restrict__ reg_out,
                        const float* __restrict__ W_cls,
                        const float* __restrict__ b_cls,
                        float* __restrict__ y_pred) {
    __shared__ float rows[C_ROWS][304];
    __shared__ float lg[C_ROWS][192];

    const int m0  = blockIdx.x * C_ROWS;
    const int tid = threadIdx.x;

    for (int p = tid; p < C_ROWS * N_REG; p += 256) {
        int mi = p / N_REG, n = p % N_REG;
        rows[mi][n] = reg_out[(size_t)(m0 + mi) * N_REG + n];
    }
    __syncthreads();

    // logits: 720 items over 256 threads; 2 independent accumulator chains
    for (int q = tid; q < C_ROWS * N_CLS; q += 256) {
        int mi = q / N_CLS, n = q % N_CLS;
        const float4* w  = (const float4*)(W_cls + (size_t)n * N_REG);
        const float4* rr = (const float4*)rows[mi];
        float s0 = b_cls[n], s1 = 0.f;
        #pragma unroll 5
        for (int k4 = 0; k4 < N_REG / 4; k4++) {
            float4 a = rr[k4];
            float4 b = __ldg(&w[k4]);
            s0 = fmaf(a.x, b.x, s0);
            s1 = fmaf(a.y, b.y, s1);
            s0 = fmaf(a.z, b.z, s0);
            s1 = fmaf(a.w, b.w, s1);
        }
        lg[mi][n] = s0 + s1;
    }
    __syncthreads();

    // softmax: one warp per row (warps 4..7 idle)
    int w = tid >> 5, lane = tid & 31;
    if (w < C_ROWS) {
        int mi = w;
        float mx = -1e30f;
        for (int n = lane; n < N_CLS; n += 32) mx = fmaxf(mx, lg[mi][n]);
        #pragma unroll
        for (int off = 16; off > 0; off >>= 1)
            mx = fmaxf(mx, __shfl_xor_sync(0xffffffff, mx, off));
        float sum = 0.f;
        for (int n = lane; n < N_CLS; n += 32) {
            float e = expf(lg[mi][n] - mx);
            lg[mi][n] = e;
            sum += e;
        }
        #pragma unroll
        for (int off = 16; off > 0; off >>= 1)
            sum += __shfl_xor_sync(0xffffffff, sum, off);
        float inv = 1.f / sum;
        for (int n = lane; n < N_CLS; n += 32)
            y_pred[(size_t)(m0 + mi) * N_CLS + n] = lg[mi][n] * inv;
    }
}

// ============================================================
// Launch
// ============================================================
extern "C" void kernel_launch(void* const* d_in, const int* in_sizes, int n_in,
                              void* d_out, int out_size) {
    const float* x     = (const float*)d_in[0];
    const float* W_enc = (const float*)d_in[1];
    const float* b_enc = (const float*)d_in[2];
    const float* gamma = (const float*)d_in[3];
    const float* beta  = (const float*)d_in[4];
    const float* rmean = (const float*)d_in[5];
    const float* rvar  = (const float*)d_in[6];
    const float* W_reg = (const float*)d_in[7];
    const float* b_reg = (const float*)d_in[8];
    const float* W_cls = (const float*)d_in[9];
    const float* b_cls = (const float*)d_in[10];
    const int*   idx   = (const int*)d_in[11];
    const int*   srci  = (const int*)d_in[12];

    const int total   = in_sizes[0] / BATCH;
    const int max_out = in_sizes[2] / NUM_ROIS;
    const int max_in  = in_sizes[11] / NUM_ROIS;
    const int C       = in_sizes[12];

    float* out        = (float*)d_out;
    float* concat_out = out;
    float* reg_out    = out + (size_t)BATCH * C;
    float* y_pred     = reg_out + (size_t)BATCH * N_REG;

    cudaFuncSetAttribute(roi_enc_kernel,
                         cudaFuncAttributeMaxDynamicSharedMemorySize, A_SMEM);
    cudaFuncSetAttribute(reg_gemm_kernel,
                         cudaFuncAttributeMaxDynamicSharedMemorySize, B_SMEM);

    setup_kernel<<<1, 512>>>(idx, srci, max_in, max_out, total, C);

    dim3 gA(NUM_ROIS, BATCH / 256, 2);
    roi_enc_kernel<<<gA, 256, A_SMEM>>>(x, W_enc, b_enc, gamma, beta, rmean, rvar,
                                        concat_out, total, max_in, max_out, C);

    dim3 gB(BATCH / 128, (N_REG + 127) / 128, SPLITK);
    reg_gemm_kernel<<<gB, 256, B_SMEM>>>(concat_out, W_reg, C);

    reg_reduce_kernel<<<(BATCH * N_REG + 255) / 256, 256>>>(b_reg, reg_out);

    cls_softmax_kernel<<<BATCH / C_ROWS, 256>>>(reg_out, W_cls, b_cls, y_pred);
}